// round 4
// baseline (speedup 1.0000x reference)
#include <cuda_runtime.h>
#include <cuda_bf16.h>
#include <math.h>
#include <stdint.h>

// Problem constants
#define Dd 32
#define Hh 1024
#define Ll 2
#define Bb 4096

typedef __nv_bfloat16 bf16;

// ---------------- device scratch (static, no allocation) ----------------
__device__ float g_pre0[Bb * Hh];       // layer-0 pre-activations (fp32, incremental)
__device__ bf16  g_p0hi[Bb * Hh];       // split(relu(pre0)) hi
__device__ bf16  g_p0lo[Bb * Hh];       // split(relu(pre0)) lo
__device__ bf16  g_a1hi[Bb * Hh];       // layer-1 activation split hi
__device__ bf16  g_a1lo[Bb * Hh];       // layer-1 activation split lo
__device__ float g_a2[Bb * Hh];         // layer-2 activation (fp32, post-relu)
__device__ bf16  g_Wh_hi[Ll * Hh * Hh]; // masked+sorted hidden weights, bf16 hi
__device__ bf16  g_Wh_lo[Ll * Hh * Hh]; // bf16 lo residual
__device__ float g_bhs[Ll * Hh];        // permuted hidden biases
__device__ float g_W0sT[Dd * Hh];       // masked, sorted W0, transposed [D][H]
__device__ float g_Wos[2 * Dd * Hh];    // masked output weights, sorted cols

// Degree-sorted permutation. Hidden degree of original unit i is i % 31.
__device__ __forceinline__ int permS(int s) {
    return (s < 34) ? 31 * s : ((s - 1) / 33) + 31 * ((s - 1) % 33);
}
__device__ __forceinline__ int degS(int s) {
    return (s < 34) ? 0 : (s - 1) / 33;
}
static inline int prefixH(int idx) { return (idx == 0) ? 0 : (33 * idx + 1); }

// ---------------- weight pre-transform ----------------
__global__ void prep_kernel(const float* __restrict__ W0,
                            const float* __restrict__ Wh,
                            const float* __restrict__ bh,
                            const float* __restrict__ Wout) {
    int stride = gridDim.x * blockDim.x;
    int tid0 = blockIdx.x * blockDim.x + threadIdx.x;

    for (int i = tid0; i < Ll * Hh * Hh; i += stride) {
        int l = i >> 20;
        int rem = i & (Hh * Hh - 1);
        int s = rem >> 10;
        int t = rem & (Hh - 1);
        float v = 0.f;
        if (degS(s) >= degS(t)) v = Wh[l * Hh * Hh + permS(s) * Hh + permS(t)];
        bf16 hi = __float2bfloat16_rn(v);
        g_Wh_hi[i] = hi;
        g_Wh_lo[i] = __float2bfloat16_rn(v - __bfloat162float(hi));
    }
    for (int i = tid0; i < Ll * Hh; i += stride) {
        int l = i >> 10;
        int s = i & (Hh - 1);
        g_bhs[i] = bh[l * Hh + permS(s)];
    }
    for (int i = tid0; i < Dd * Hh; i += stride) {
        int j = i >> 10;
        int s = i & (Hh - 1);
        g_W0sT[i] = (degS(s) >= j) ? W0[permS(s) * Dd + j] : 0.f;
    }
    for (int i = tid0; i < 2 * Dd * Hh; i += stride) {
        int o = i >> 10;
        int t = i & (Hh - 1);
        g_Wos[i] = (((o & 31) - 1) >= degS(t)) ? Wout[o * Hh + permS(t)] : 0.f;
    }
}

__global__ void init_kernel(const float* __restrict__ b0) {
    int stride = gridDim.x * blockDim.x;
    int tid0 = blockIdx.x * blockDim.x + threadIdx.x;
    for (int i = tid0; i < Bb * Hh; i += stride) {
        int s = i & (Hh - 1);
        float v = b0[permS(s)];
        g_pre0[i] = v;
        float y = fmaxf(v, 0.f);
        bf16 hi = __float2bfloat16_rn(y);
        g_p0hi[i] = hi;
        g_p0lo[i] = __float2bfloat16_rn(y - __bfloat162float(hi));
        g_a1hi[i] = __float2bfloat16_rn(0.f);
        g_a1lo[i] = __float2bfloat16_rn(0.f);
        g_a2[i] = 0.f;
    }
}

// ---------------- bf16 TC GEMM, split inputs, cp.async double-buffered ----------
// out = relu(A @ W^T + bias); A given pre-split (hi/lo bf16), W pre-split.
// OUTMODE 0: write fp32 out. OUTMODE 1: write bf16 split (hi/lo) post-relu.
#define BM 128
#define BN 64
#define BK 32
#define APAD 40   // bf16 per smem row (80B) -> conflict-free ldmatrix

#define SM_AH 0
#define SM_AL (BM * APAD)
#define SM_BH (2 * BM * APAD)
#define SM_BL (2 * BM * APAD + BN * APAD)
#define SM_STAGE (2 * BM * APAD + 2 * BN * APAD)   // 15360 bf16 per stage
#define SMEM_BYTES (2 * SM_STAGE * 2)              // 61440 bytes

__device__ __forceinline__ uint32_t smem_u32(const void* p) {
    return (uint32_t)__cvta_generic_to_shared(p);
}
__device__ __forceinline__ void cp16(uint32_t dst, const void* src) {
    asm volatile("cp.async.cg.shared.global [%0], [%1], 16;\n" :: "r"(dst), "l"(src));
}
__device__ __forceinline__ void cp_commit() {
    asm volatile("cp.async.commit_group;\n");
}
__device__ __forceinline__ void cp_wait1() {
    asm volatile("cp.async.wait_group 1;\n");
}
__device__ __forceinline__ void ldsm4(uint32_t& r0, uint32_t& r1, uint32_t& r2,
                                      uint32_t& r3, uint32_t addr) {
    asm volatile("ldmatrix.sync.aligned.m8n8.x4.shared.b16 {%0,%1,%2,%3}, [%4];\n"
                 : "=r"(r0), "=r"(r1), "=r"(r2), "=r"(r3) : "r"(addr));
}
__device__ __forceinline__ void mma_bf16(float c[4], const uint32_t a[4], const uint32_t b[2]) {
    asm volatile(
        "mma.sync.aligned.m16n8k16.row.col.f32.bf16.bf16.f32 "
        "{%0,%1,%2,%3}, {%4,%5,%6,%7}, {%8,%9}, {%0,%1,%2,%3};\n"
        : "+f"(c[0]), "+f"(c[1]), "+f"(c[2]), "+f"(c[3])
        : "r"(a[0]), "r"(a[1]), "r"(a[2]), "r"(a[3]), "r"(b[0]), "r"(b[1]));
}

template <int OUTMODE>
__global__ __launch_bounds__(256) void gemm_tc(const bf16* __restrict__ Ahi,
                                               const bf16* __restrict__ Alo,
                                               const bf16* __restrict__ Whi,
                                               const bf16* __restrict__ Wlo,
                                               const float* __restrict__ bias,
                                               float* __restrict__ outF,
                                               bf16* __restrict__ outHi,
                                               bf16* __restrict__ outLo,
                                               int h) {
    extern __shared__ bf16 sm[];

    const int m0 = blockIdx.x * BM;
    const int n0 = blockIdx.y * BN;

    // triangular K-limit for this N-tile
    int s1 = min(n0 + BN - 1, h - 1);
    int g1 = (s1 < 34) ? 0 : (s1 - 1) / 33;
    int kmax = min(h, 33 * g1 + 34);
    kmax = (kmax + BK - 1) & ~(BK - 1);
    const int nIter = kmax / BK;

    const int tid = (int)threadIdx.x;
    const int lane = tid & 31;
    const int wid = tid >> 5;
    const int wm = wid & 3;
    const int wn = wid >> 2;
    const int g = lane >> 2;
    const int tg = lane & 3;

    // cp.async staging indices
    const int aIdx = tid;               // base for A (1024 chunk-slots, 4 per thread)
    // prefetch one stage: A hi/lo (128 rows x 4 chunks x 2) + B hi/lo (64 x 4 x 2)
    auto prefetch = [&](int stage, int k0) {
        uint32_t sbase = smem_u32(sm) + (uint32_t)(stage * SM_STAGE) * 2u;
#pragma unroll
        for (int i = 0; i < 4; i++) {
            int idx = aIdx + i * 256;          // 0..1023
            int half = idx >> 9;               // 0: hi, 1: lo
            int r = (idx & 511) >> 2;
            int ch = idx & 3;
            const bf16* src = (half ? Alo : Ahi) + (size_t)(m0 + r) * Hh + k0 + ch * 8;
            uint32_t dst = sbase + (uint32_t)((half ? SM_AL : SM_AH) + r * APAD + ch * 8) * 2u;
            cp16(dst, src);
        }
#pragma unroll
        for (int i = 0; i < 2; i++) {
            int idx = aIdx + i * 256;          // 0..511
            int half = idx >> 8;
            int r = (idx & 255) >> 2;
            int ch = idx & 3;
            const bf16* src = (half ? Wlo : Whi) + (size_t)(n0 + r) * Hh + k0 + ch * 8;
            uint32_t dst = sbase + (uint32_t)((half ? SM_BL : SM_BH) + r * APAD + ch * 8) * 2u;
            cp16(dst, src);
        }
    };

    float c[2][4][4];
#pragma unroll
    for (int mi = 0; mi < 2; mi++)
#pragma unroll
        for (int ni = 0; ni < 4; ni++)
#pragma unroll
            for (int q = 0; q < 4; q++) c[mi][ni][q] = 0.f;

    const int lrow = lane & 15;
    const int lkof = (lane >> 4) << 3;

    prefetch(0, 0);
    cp_commit();

    for (int it = 0; it < nIter; it++) {
        const int buf = it & 1;
        if (it + 1 < nIter) prefetch(buf ^ 1, (it + 1) * BK);
        cp_commit();
        cp_wait1();
        __syncthreads();

        uint32_t sbase = smem_u32(sm) + (uint32_t)(buf * SM_STAGE) * 2u;
        const uint32_t sAhi = sbase;
        const uint32_t sAlo = sbase + (uint32_t)SM_AL * 2u;
        const uint32_t sBhi = sbase + (uint32_t)SM_BH * 2u;
        const uint32_t sBlo = sbase + (uint32_t)SM_BL * 2u;

#pragma unroll
        for (int kst = 0; kst < 2; kst++) {
            const int ks = kst * 16;
            uint32_t ah[2][4], al[2][4];
#pragma unroll
            for (int mi = 0; mi < 2; mi++) {
                int row = wm * 32 + mi * 16 + lrow;
                uint32_t off = (uint32_t)(row * APAD + ks + lkof) * 2u;
                ldsm4(ah[mi][0], ah[mi][1], ah[mi][2], ah[mi][3], sAhi + off);
                ldsm4(al[mi][0], al[mi][1], al[mi][2], al[mi][3], sAlo + off);
            }
            uint32_t bh[4][2], bl[4][2];
#pragma unroll
            for (int nj = 0; nj < 2; nj++) {
                int nrow = wn * 32 + nj * 16 + lrow;
                uint32_t off = (uint32_t)(nrow * APAD + ks + lkof) * 2u;
                uint32_t t0, t1, t2, t3;
                ldsm4(t0, t1, t2, t3, sBhi + off);
                bh[nj * 2][0] = t0; bh[nj * 2 + 1][0] = t1;
                bh[nj * 2][1] = t2; bh[nj * 2 + 1][1] = t3;
                ldsm4(t0, t1, t2, t3, sBlo + off);
                bl[nj * 2][0] = t0; bl[nj * 2 + 1][0] = t1;
                bl[nj * 2][1] = t2; bl[nj * 2 + 1][1] = t3;
            }
#pragma unroll
            for (int mi = 0; mi < 2; mi++)
#pragma unroll
                for (int ni = 0; ni < 4; ni++) {
                    mma_bf16(c[mi][ni], ah[mi], bh[ni]);
                    mma_bf16(c[mi][ni], al[mi], bh[ni]);
                    mma_bf16(c[mi][ni], ah[mi], bl[ni]);
                }
        }
        __syncthreads();
    }

    // ---- epilogue ----
#pragma unroll
    for (int mi = 0; mi < 2; mi++) {
        int r0 = m0 + wm * 32 + mi * 16 + g;
#pragma unroll
        for (int ni = 0; ni < 4; ni++) {
            int col = n0 + wn * 32 + ni * 8 + tg * 2;
#pragma unroll
            for (int q = 0; q < 2; q++) {       // q: col offset 0/1
                int cc = col + q;
                if (cc < h) {
                    float bv = bias[cc];
                    float y0 = fmaxf(c[mi][ni][q] + bv, 0.f);         // row r0
                    float y1 = fmaxf(c[mi][ni][q + 2] + bv, 0.f);     // row r0+8
                    if (OUTMODE == 0) {
                        outF[(size_t)r0 * Hh + cc] = y0;
                        outF[(size_t)(r0 + 8) * Hh + cc] = y1;
                    } else {
                        bf16 h0 = __float2bfloat16_rn(y0);
                        bf16 h1 = __float2bfloat16_rn(y1);
                        outHi[(size_t)r0 * Hh + cc] = h0;
                        outHi[(size_t)(r0 + 8) * Hh + cc] = h1;
                        outLo[(size_t)r0 * Hh + cc] =
                            __float2bfloat16_rn(y0 - __bfloat162float(h0));
                        outLo[(size_t)(r0 + 8) * Hh + cc] =
                            __float2bfloat16_rn(y1 - __bfloat162float(h1));
                    }
                }
            }
        }
    }
}

// ---------------- fused output + state update per step ----------------
__global__ __launch_bounds__(128) void finish_kernel(const float* __restrict__ z,
                                                     const float* __restrict__ bout,
                                                     float* __restrict__ x,
                                                     int idx, int h) {
    int r = blockIdx.x;
    int t = (int)threadIdx.x;
    const float* arow = g_a2 + (size_t)r * Hh;
    const float* wmu = g_Wos + (size_t)idx * Hh;
    const float* wls = g_Wos + (size_t)(idx + Dd) * Hh;

    float smu = 0.f, sls = 0.f;
    for (int ccol = t; ccol < h; ccol += 128) {
        float av = arow[ccol];
        smu += av * wmu[ccol];
        sls += av * wls[ccol];
    }
#pragma unroll
    for (int off = 16; off; off >>= 1) {
        smu += __shfl_down_sync(0xffffffffu, smu, off);
        sls += __shfl_down_sync(0xffffffffu, sls, off);
    }
    __shared__ float rmu[4], rls[4];
    __shared__ float s_xi;
    if ((t & 31) == 0) { rmu[t >> 5] = smu; rls[t >> 5] = sls; }
    __syncthreads();
    if (t == 0) {
        float mu = rmu[0] + rmu[1] + rmu[2] + rmu[3] + bout[idx];
        float ls = rls[0] + rls[1] + rls[2] + rls[3] + bout[idx + Dd];
        float xi = z[(size_t)r * Dd + idx] * expf(ls) + mu;
        x[(size_t)r * Dd + idx] = xi;
        s_xi = xi;
    }
    __syncthreads();
    float xi = s_xi;
    const float* w0col = g_W0sT + idx * Hh;
    float* prow = g_pre0 + (size_t)r * Hh;
    bf16* phrow = g_p0hi + (size_t)r * Hh;
    bf16* plrow = g_p0lo + (size_t)r * Hh;
    // only suffix s >= h has nonzero W0 column; maintain fp32 + split(relu)
    for (int s = h + t; s < Hh; s += 128) {
        float v = prow[s] + w0col[s] * xi;
        prow[s] = v;
        float y = fmaxf(v, 0.f);
        bf16 hi = __float2bfloat16_rn(y);
        phrow[s] = hi;
        plrow[s] = __float2bfloat16_rn(y - __bfloat162float(hi));
    }
}

// ---------------- launch ----------------
extern "C" void kernel_launch(void* const* d_in, const int* in_sizes, int n_in,
                              void* d_out, int out_size) {
    const float* z    = (const float*)d_in[0];
    const float* W0   = (const float*)d_in[1];
    const float* b0   = (const float*)d_in[2];
    const float* Wh   = (const float*)d_in[3];
    const float* bh   = (const float*)d_in[4];
    const float* Wout = (const float*)d_in[5];
    const float* bout = (const float*)d_in[6];
    float* x = (float*)d_out;

    static int attrSet = 0;
    if (!attrSet) {
        cudaFuncSetAttribute(gemm_tc<0>, cudaFuncAttributeMaxDynamicSharedMemorySize, SMEM_BYTES);
        cudaFuncSetAttribute(gemm_tc<1>, cudaFuncAttributeMaxDynamicSharedMemorySize, SMEM_BYTES);
        attrSet = 1;
    }

    prep_kernel<<<1024, 256>>>(W0, Wh, bh, Wout);
    init_kernel<<<1024, 256>>>(b0);

    float *pre0, *a2, *bhs;
    bf16 *p0hi, *p0lo, *a1hi, *a1lo, *Whi, *Wlo;
    cudaGetSymbolAddress((void**)&pre0, g_pre0);
    cudaGetSymbolAddress((void**)&p0hi, g_p0hi);
    cudaGetSymbolAddress((void**)&p0lo, g_p0lo);
    cudaGetSymbolAddress((void**)&a1hi, g_a1hi);
    cudaGetSymbolAddress((void**)&a1lo, g_a1lo);
    cudaGetSymbolAddress((void**)&a2, g_a2);
    cudaGetSymbolAddress((void**)&Whi, g_Wh_hi);
    cudaGetSymbolAddress((void**)&Wlo, g_Wh_lo);
    cudaGetSymbolAddress((void**)&bhs, g_bhs);

    for (int idx = 0; idx < Dd; idx++) {
        int h = prefixH(idx);
        if (h > 0) {
            dim3 grid(Bb / BM, (h + BN - 1) / BN);
            // layer 1: A = split(relu(pre0)) -> write a1 split (relu fused)
            gemm_tc<1><<<grid, 256, SMEM_BYTES>>>(p0hi, p0lo, Whi, Wlo, bhs,
                                                  nullptr, a1hi, a1lo, h);
            // layer 2: A = a1 split -> write a2 fp32 (relu fused)
            gemm_tc<0><<<grid, 256, SMEM_BYTES>>>(a1hi, a1lo, Whi + Hh * Hh,
                                                  Wlo + Hh * Hh, bhs + Hh, a2,
                                                  nullptr, nullptr, h);
        }
        finish_kernel<<<Bb, 128>>>(z, bout, x, idx, h);
    }
}